// round 9
// baseline (speedup 1.0000x reference)
#include <cuda_runtime.h>
#include <cuda_bf16.h>
#include <cstdint>

// RNNModel: T=512, B=256, I=256, H=512, fp32.
//   K1: xp = x @ w_ih^T + (b_ih + b_hh)      -> mma.sync 3xTF32 GEMM (2 CTA/SM)
//   K2: h_t = tanh(xp_t + h_{t-1} @ w_hh^T)  -> persistent; warps split N (no reduce), b-major hT
//   K3: out = hs @ w_fc^T + b_fc             -> mma.sync 3xTF32 GEMM

#define T_ 512
#define B_ 256
#define I_ 256
#define H_ 512

#define NG  16
#define NSL 8
#define BT  16
#define NS  64
#define WPAD 68
#define HSTR 516   // b-major hT row stride (floats); 516*4 % 16 == 0, bank-spread

__device__ float g_xp[(size_t)T_ * B_ * H_];
__device__ float g_hs[(size_t)T_ * B_ * H_];
__device__ int   g_cnt[NG];

// ---------------- helpers ----------------
__device__ __forceinline__ unsigned long long f32x2_fma(unsigned long long a,
                                                        unsigned long long b,
                                                        unsigned long long c) {
    unsigned long long d;
    asm("fma.rn.f32x2 %0, %1, %2, %3;" : "=l"(d) : "l"(a), "l"(b), "l"(c));
    return d;
}
__device__ __forceinline__ unsigned long long f32x2_splat(float x) {
    unsigned long long d;
    unsigned int xi = __float_as_uint(x);
    asm("mov.b64 %0, {%1, %1};" : "=l"(d) : "r"(xi));
    return d;
}
__device__ __forceinline__ float2 f32x2_unpack(unsigned long long v) {
    unsigned int lo, hi;
    asm("mov.b64 {%0, %1}, %2;" : "=r"(lo), "=r"(hi) : "l"(v));
    float2 r;
    r.x = __uint_as_float(lo);
    r.y = __uint_as_float(hi);
    return r;
}
__device__ __forceinline__ uint32_t smem_u32(const void* p) {
    uint32_t a;
    asm("{ .reg .u64 t; cvta.to.shared.u64 t, %1; cvt.u32.u64 %0, t; }" : "=r"(a) : "l"(p));
    return a;
}
__device__ __forceinline__ void cp_async16(uint32_t saddr, const void* gptr) {
    asm volatile("cp.async.ca.shared.global [%0], [%1], 16;" :: "r"(saddr), "l"(gptr));
}
#define CP_COMMIT_WAIT() \
    asm volatile("cp.async.commit_group;\n\tcp.async.wait_group 0;" ::: "memory")

// ---------------- tf32 helpers ----------------
__device__ __forceinline__ uint32_t cvt_tf32(float x) {
    uint32_t r;
    asm("cvt.rna.tf32.f32 %0, %1;" : "=r"(r) : "f"(x));
    return r;
}
__device__ __forceinline__ void split_tf32(float x, float& big, float& small) {
    big = __uint_as_float(cvt_tf32(x));
    small = __uint_as_float(cvt_tf32(x - big));
}
__device__ __forceinline__ void mma16n8k8(float* c, const uint32_t* a, const uint32_t* b) {
    asm volatile("mma.sync.aligned.m16n8k8.row.col.f32.tf32.tf32.f32 "
        "{%0,%1,%2,%3}, {%4,%5,%6,%7}, {%8,%9}, {%0,%1,%2,%3};"
        : "+f"(c[0]), "+f"(c[1]), "+f"(c[2]), "+f"(c[3])
        : "r"(a[0]), "r"(a[1]), "r"(a[2]), "r"(a[3]), "r"(b[0]), "r"(b[1]));
}

// ---------------- K1/K3: 3xTF32 mma.sync GEMM (now 2 CTA/SM) ----------------
#define KCHUNK 16
#define PADS 20
#define ARRF (128 * PADS)
#define STGF (4 * ARRF)
#define GEMM_SMEM_BYTES (2 * STGF * 4)   // 81920

__global__ void __launch_bounds__(256, 2) mma_gemm_kernel(
    const float* __restrict__ A, const float* __restrict__ Bm,
    const float* __restrict__ b1, const float* __restrict__ b2,
    float* __restrict__ C, int M, int N, int K)
{
    extern __shared__ float sh[];
    const int tid = threadIdx.x;
    const int m0 = blockIdx.y << 7;
    const int n0 = blockIdx.x << 7;
    const int lane = tid & 31, wid = tid >> 5;
    const int gid = lane >> 2, tig = lane & 3;
    const int wm = wid >> 1, wn = wid & 1;

    const int lrow = tid >> 1;
    const int lko  = (tid & 1) << 3;

    const float* Ap = A + (size_t)(m0 + lrow) * K + lko;
    const float* Bp = Bm + (size_t)(n0 + lrow) * K + lko;

    float acc[2][8][4];
#pragma unroll
    for (int mt = 0; mt < 2; mt++)
#pragma unroll
        for (int nt = 0; nt < 8; nt++)
#pragma unroll
            for (int i = 0; i < 4; i++) acc[mt][nt][i] = 0.0f;

    const int NC = K >> 4;

    float4 ar0 = *(const float4*)(Ap);
    float4 ar1 = *(const float4*)(Ap + 4);
    float4 br0 = *(const float4*)(Bp);
    float4 br1 = *(const float4*)(Bp + 4);

    for (int kc = 0; kc < NC; kc++) {
        const int s = kc & 1;
        float* AB = sh + s * STGF;
        float* AS = AB + ARRF;
        float* BB = AS + ARRF;
        float* BS = BB + ARRF;

        {
            float4 bg, sm;
            const int sa = lrow * PADS + lko;
            split_tf32(ar0.x, bg.x, sm.x); split_tf32(ar0.y, bg.y, sm.y);
            split_tf32(ar0.z, bg.z, sm.z); split_tf32(ar0.w, bg.w, sm.w);
            *(float4*)(AB + sa) = bg; *(float4*)(AS + sa) = sm;
            split_tf32(ar1.x, bg.x, sm.x); split_tf32(ar1.y, bg.y, sm.y);
            split_tf32(ar1.z, bg.z, sm.z); split_tf32(ar1.w, bg.w, sm.w);
            *(float4*)(AB + sa + 4) = bg; *(float4*)(AS + sa + 4) = sm;
            split_tf32(br0.x, bg.x, sm.x); split_tf32(br0.y, bg.y, sm.y);
            split_tf32(br0.z, bg.z, sm.z); split_tf32(br0.w, bg.w, sm.w);
            *(float4*)(BB + sa) = bg; *(float4*)(BS + sa) = sm;
            split_tf32(br1.x, bg.x, sm.x); split_tf32(br1.y, bg.y, sm.y);
            split_tf32(br1.z, bg.z, sm.z); split_tf32(br1.w, bg.w, sm.w);
            *(float4*)(BB + sa + 4) = bg; *(float4*)(BS + sa + 4) = sm;
        }
        __syncthreads();

        if (kc + 1 < NC) {
            const int K0 = (kc + 1) << 4;
            ar0 = *(const float4*)(Ap + K0);
            ar1 = *(const float4*)(Ap + K0 + 4);
            br0 = *(const float4*)(Bp + K0);
            br1 = *(const float4*)(Bp + K0 + 4);
        }

#pragma unroll
        for (int lk8 = 0; lk8 < KCHUNK; lk8 += 8) {
            uint32_t ab[2][4], as_[2][4], bb[8][2], bs[8][2];
#pragma unroll
            for (int mt = 0; mt < 2; mt++) {
                const int r = (wm << 5) + (mt << 4) + gid;
                ab[mt][0]  = __float_as_uint(AB[r * PADS + lk8 + tig]);
                ab[mt][1]  = __float_as_uint(AB[(r + 8) * PADS + lk8 + tig]);
                ab[mt][2]  = __float_as_uint(AB[r * PADS + lk8 + tig + 4]);
                ab[mt][3]  = __float_as_uint(AB[(r + 8) * PADS + lk8 + tig + 4]);
                as_[mt][0] = __float_as_uint(AS[r * PADS + lk8 + tig]);
                as_[mt][1] = __float_as_uint(AS[(r + 8) * PADS + lk8 + tig]);
                as_[mt][2] = __float_as_uint(AS[r * PADS + lk8 + tig + 4]);
                as_[mt][3] = __float_as_uint(AS[(r + 8) * PADS + lk8 + tig + 4]);
            }
#pragma unroll
            for (int nt = 0; nt < 8; nt++) {
                const int nn = (wn << 6) + (nt << 3) + gid;
                bb[nt][0] = __float_as_uint(BB[nn * PADS + lk8 + tig]);
                bb[nt][1] = __float_as_uint(BB[nn * PADS + lk8 + tig + 4]);
                bs[nt][0] = __float_as_uint(BS[nn * PADS + lk8 + tig]);
                bs[nt][1] = __float_as_uint(BS[nn * PADS + lk8 + tig + 4]);
            }
#pragma unroll
            for (int mt = 0; mt < 2; mt++)
#pragma unroll
                for (int nt = 0; nt < 8; nt++) {
                    mma16n8k8(acc[mt][nt], ab[mt], bb[nt]);
                    mma16n8k8(acc[mt][nt], as_[mt], bb[nt]);
                    mma16n8k8(acc[mt][nt], ab[mt], bs[nt]);
                }
        }
        __syncthreads();
    }

    float bias[8][2];
#pragma unroll
    for (int nt = 0; nt < 8; nt++) {
        const int col = n0 + (wn << 6) + (nt << 3) + (tig << 1);
        float v0 = b1[col], v1 = b1[col + 1];
        if (b2) { v0 += b2[col]; v1 += b2[col + 1]; }
        bias[nt][0] = v0; bias[nt][1] = v1;
    }
#pragma unroll
    for (int mt = 0; mt < 2; mt++)
#pragma unroll
        for (int half = 0; half < 2; half++) {
            const int row = m0 + (wm << 5) + (mt << 4) + gid + (half << 3);
            float* crow = C + (size_t)row * N;
#pragma unroll
            for (int nt = 0; nt < 8; nt++) {
                const int col = n0 + (wn << 6) + (nt << 3) + (tig << 1);
                float2 v;
                v.x = acc[mt][nt][half * 2 + 0] + bias[nt][0];
                v.y = acc[mt][nt][half * 2 + 1] + bias[nt][1];
                *(float2*)(crow + col) = v;
            }
        }
}

// ---------------- init ----------------
__global__ void zero_cnt_kernel() {
    if (threadIdx.x < NG) g_cnt[threadIdx.x] = 0;
}

// ---------------- K2: persistent recurrence, N-split warps ----------------
// 128 CTAs = 16 groups x 8 slices, 1/SM (smem 172KB). Warp w owns output cols
// [w*8, w*8+8) over FULL K=512 -> final accumulators in registers, no reduction.
// hT is b-major: staging is a straight 32KB cp.async memcpy (conflict-free);
// compute reads h as broadcast float4 and W as 2-address broadcast ulonglong2.
__global__ void __launch_bounds__(256) rnn_rec_kernel(const float* __restrict__ w_hh)
{
    extern __shared__ float sm[];
    float* w_t = sm;                 // [512][WPAD] k-major W slice
    float* hT  = sm + H_ * WPAD;     // [BT][HSTR]  b-major h tile

    const int tid = threadIdx.x;
    const int g = blockIdx.x >> 3;
    const int s = blockIdx.x & 7;
    const int n0 = s * NS;
    const int b0 = g * BT;

    // cache W_hh slice: w_t[k][n] = w_hh[n0+n][k]
    for (int i = tid; i < NS * H_; i += 256) {
        int n = i >> 9;
        int k = i & (H_ - 1);
        w_t[k * WPAD + n] = w_hh[(size_t)(n0 + n) * H_ + k];
    }

    const int wid = tid >> 5, lane = tid & 31;
    const int b  = lane >> 1;        // batch row (0..15)
    const int nh = lane & 1;         // col half (0/1)
    const int c0 = wid * 8 + nh * 4; // 4 output cols

    const size_t obase = ((size_t)(b0 + b)) * H_ + n0 + c0;
    const uint32_t hT_u32 = smem_u32(hT);

    __syncthreads();

    for (int t = 0; t < T_; t++) {
        // prefetch xp[t] (independent of the flag)
        const float4 xv = __ldcs((const float4*)&g_xp[(size_t)t * B_ * H_ + obase]);

        // --- acquire h_{t-1} ---
        if (t > 0) {
            if (tid == 0) {
                volatile int* c = g_cnt + g;
                while (*c < NSL * t) __nanosleep(40);
                __threadfence();
            }
            __syncthreads();
            const float* hsrc = g_hs + ((size_t)(t - 1) * B_ + b0) * H_;
#pragma unroll
            for (int j = 0; j < 8; j++) {
                int i4 = tid + (j << 8);          // float4 index 0..2047
                int bb = i4 >> 7;                 // batch row
                int k4 = i4 & 127;                // float4 within row
                cp_async16(hT_u32 + (uint32_t)(bb * HSTR + k4 * 4) * 4,
                           hsrc + (size_t)i4 * 4);
            }
            CP_COMMIT_WAIT();
        } else {
            for (int i = tid; i < BT * HSTR; i += 256) hT[i] = 0.0f;
        }
        __syncthreads();

        // --- compute 4 output cols for batch row b over full K ---
        unsigned long long a0 = 0ull, a1 = 0ull;
        const float* hrow = hT + b * HSTR;
        const float* wcol = w_t + c0;
#pragma unroll 4
        for (int k4 = 0; k4 < 128; k4++) {
            const float4 hv = *(const float4*)(hrow + (k4 << 2));
            const float hh[4] = {hv.x, hv.y, hv.z, hv.w};
#pragma unroll
            for (int c = 0; c < 4; c++) {
                const ulonglong2 wv = *(const ulonglong2*)(wcol + ((k4 << 2) + c) * WPAD);
                const unsigned long long hs2 = f32x2_splat(hh[c]);
                a0 = f32x2_fma(hs2, wv.x, a0);
                a1 = f32x2_fma(hs2, wv.y, a1);
            }
        }

        // --- epilogue: add xp, tanh, store h_t (no cross-warp reduce needed) ---
        {
            const float2 lo = f32x2_unpack(a0);
            const float2 hi = f32x2_unpack(a1);
            float4 r;
            r.x = tanhf(lo.x + xv.x);
            r.y = tanhf(lo.y + xv.y);
            r.z = tanhf(hi.x + xv.z);
            r.w = tanhf(hi.y + xv.w);
            *(float4*)&g_hs[(size_t)t * B_ * H_ + obase] = r;
        }
        __syncthreads();

        // --- release slice s of step t ---
        if (tid == 0) {
            __threadfence();
            atomicAdd(&g_cnt[g], 1);
        }
    }
}

// ---------------- launch ----------------
extern "C" void kernel_launch(void* const* d_in, const int* in_sizes, int n_in,
                              void* d_out, int out_size)
{
    const float* x    = (const float*)d_in[0];
    const float* w_ih = (const float*)d_in[1];
    const float* w_hh = (const float*)d_in[2];
    const float* b_ih = (const float*)d_in[3];
    const float* b_hh = (const float*)d_in[4];
    const float* w_fc = (const float*)d_in[5];
    const float* b_fc = (const float*)d_in[6];
    float* out = (float*)d_out;

    float* xp = nullptr;
    float* hs = nullptr;
    cudaGetSymbolAddress((void**)&xp, g_xp);
    cudaGetSymbolAddress((void**)&hs, g_hs);

    const int rec_smem = (H_ * WPAD + BT * HSTR) * (int)sizeof(float); // 172288
    cudaFuncSetAttribute(rnn_rec_kernel, cudaFuncAttributeMaxDynamicSharedMemorySize, rec_smem);
    cudaFuncSetAttribute(mma_gemm_kernel, cudaFuncAttributeMaxDynamicSharedMemorySize, GEMM_SMEM_BYTES);

    const int M = T_ * B_;

    zero_cnt_kernel<<<1, 32>>>();

    // K1: xp = x @ w_ih^T + (b_ih + b_hh)
    mma_gemm_kernel<<<dim3(H_ / 128, M / 128), 256, GEMM_SMEM_BYTES>>>(x, w_ih, b_ih, b_hh, xp, M, H_, I_);

    // K2: recurrence (persistent, 128 CTAs)
    rnn_rec_kernel<<<NG * NSL, 256, rec_smem>>>(w_hh);

    // K3: out = hs @ w_fc^T + b_fc
    mma_gemm_kernel<<<dim3(I_ / 128, M / 128), 256, GEMM_SMEM_BYTES>>>(hs, w_fc, b_fc, nullptr, out, M, I_, H_);
}

// round 10
// speedup vs baseline: 1.0395x; 1.0395x over previous
#include <cuda_runtime.h>
#include <cuda_bf16.h>
#include <cstdint>

// RNNModel: T=512, B=256, I=256, H=512, fp32.
//   K1: xp = x @ w_ih^T + (b_ih + b_hh)      -> mma.sync 3xTF32 GEMM (2 CTA/SM)
//   K2: h_t = tanh(xp_t + h_{t-1} @ w_hh^T)  -> persistent; warps split N (no reduce), b-major hT
//   K3: out = hs @ w_fc^T + b_fc             -> mma.sync 3xTF32 GEMM

#define T_ 512
#define B_ 256
#define I_ 256
#define H_ 512

#define NG  16
#define NSL 8
#define BT  16
#define NS  64
#define WPAD 68
#define HSTR 516   // b-major hT row stride (floats); 516*4 % 16 == 0, bank-spread

__device__ float g_xp[(size_t)T_ * B_ * H_];
__device__ float g_hs[(size_t)T_ * B_ * H_];
__device__ int   g_cnt[NG];

// ---------------- helpers ----------------
__device__ __forceinline__ unsigned long long f32x2_fma(unsigned long long a,
                                                        unsigned long long b,
                                                        unsigned long long c) {
    unsigned long long d;
    asm("fma.rn.f32x2 %0, %1, %2, %3;" : "=l"(d) : "l"(a), "l"(b), "l"(c));
    return d;
}
__device__ __forceinline__ unsigned long long f32x2_splat(float x) {
    unsigned long long d;
    unsigned int xi = __float_as_uint(x);
    asm("mov.b64 %0, {%1, %1};" : "=l"(d) : "r"(xi));
    return d;
}
__device__ __forceinline__ float2 f32x2_unpack(unsigned long long v) {
    unsigned int lo, hi;
    asm("mov.b64 {%0, %1}, %2;" : "=r"(lo), "=r"(hi) : "l"(v));
    float2 r;
    r.x = __uint_as_float(lo);
    r.y = __uint_as_float(hi);
    return r;
}
__device__ __forceinline__ uint32_t smem_u32(const void* p) {
    uint32_t a;
    asm("{ .reg .u64 t; cvta.to.shared.u64 t, %1; cvt.u32.u64 %0, t; }" : "=r"(a) : "l"(p));
    return a;
}
__device__ __forceinline__ void cp_async16(uint32_t saddr, const void* gptr) {
    asm volatile("cp.async.ca.shared.global [%0], [%1], 16;" :: "r"(saddr), "l"(gptr));
}
#define CP_COMMIT_WAIT() \
    asm volatile("cp.async.commit_group;\n\tcp.async.wait_group 0;" ::: "memory")

// ---------------- tf32 helpers ----------------
__device__ __forceinline__ uint32_t cvt_tf32(float x) {
    uint32_t r;
    asm("cvt.rna.tf32.f32 %0, %1;" : "=r"(r) : "f"(x));
    return r;
}
__device__ __forceinline__ void split_tf32(float x, float& big, float& small) {
    big = __uint_as_float(cvt_tf32(x));
    small = __uint_as_float(cvt_tf32(x - big));
}
__device__ __forceinline__ void mma16n8k8(float* c, const uint32_t* a, const uint32_t* b) {
    asm volatile("mma.sync.aligned.m16n8k8.row.col.f32.tf32.tf32.f32 "
        "{%0,%1,%2,%3}, {%4,%5,%6,%7}, {%8,%9}, {%0,%1,%2,%3};"
        : "+f"(c[0]), "+f"(c[1]), "+f"(c[2]), "+f"(c[3])
        : "r"(a[0]), "r"(a[1]), "r"(a[2]), "r"(a[3]), "r"(b[0]), "r"(b[1]));
}

// ---------------- K1/K3: 3xTF32 mma.sync GEMM (now 2 CTA/SM) ----------------
#define KCHUNK 16
#define PADS 20
#define ARRF (128 * PADS)
#define STGF (4 * ARRF)
#define GEMM_SMEM_BYTES (2 * STGF * 4)   // 81920

__global__ void __launch_bounds__(256, 2) mma_gemm_kernel(
    const float* __restrict__ A, const float* __restrict__ Bm,
    const float* __restrict__ b1, const float* __restrict__ b2,
    float* __restrict__ C, int M, int N, int K)
{
    extern __shared__ float sh[];
    const int tid = threadIdx.x;
    const int m0 = blockIdx.y << 7;
    const int n0 = blockIdx.x << 7;
    const int lane = tid & 31, wid = tid >> 5;
    const int gid = lane >> 2, tig = lane & 3;
    const int wm = wid >> 1, wn = wid & 1;

    const int lrow = tid >> 1;
    const int lko  = (tid & 1) << 3;

    const float* Ap = A + (size_t)(m0 + lrow) * K + lko;
    const float* Bp = Bm + (size_t)(n0 + lrow) * K + lko;

    float acc[2][8][4];
#pragma unroll
    for (int mt = 0; mt < 2; mt++)
#pragma unroll
        for (int nt = 0; nt < 8; nt++)
#pragma unroll
            for (int i = 0; i < 4; i++) acc[mt][nt][i] = 0.0f;

    const int NC = K >> 4;

    float4 ar0 = *(const float4*)(Ap);
    float4 ar1 = *(const float4*)(Ap + 4);
    float4 br0 = *(const float4*)(Bp);
    float4 br1 = *(const float4*)(Bp + 4);

    for (int kc = 0; kc < NC; kc++) {
        const int s = kc & 1;
        float* AB = sh + s * STGF;
        float* AS = AB + ARRF;
        float* BB = AS + ARRF;
        float* BS = BB + ARRF;

        {
            float4 bg, sm;
            const int sa = lrow * PADS + lko;
            split_tf32(ar0.x, bg.x, sm.x); split_tf32(ar0.y, bg.y, sm.y);
            split_tf32(ar0.z, bg.z, sm.z); split_tf32(ar0.w, bg.w, sm.w);
            *(float4*)(AB + sa) = bg; *(float4*)(AS + sa) = sm;
            split_tf32(ar1.x, bg.x, sm.x); split_tf32(ar1.y, bg.y, sm.y);
            split_tf32(ar1.z, bg.z, sm.z); split_tf32(ar1.w, bg.w, sm.w);
            *(float4*)(AB + sa + 4) = bg; *(float4*)(AS + sa + 4) = sm;
            split_tf32(br0.x, bg.x, sm.x); split_tf32(br0.y, bg.y, sm.y);
            split_tf32(br0.z, bg.z, sm.z); split_tf32(br0.w, bg.w, sm.w);
            *(float4*)(BB + sa) = bg; *(float4*)(BS + sa) = sm;
            split_tf32(br1.x, bg.x, sm.x); split_tf32(br1.y, bg.y, sm.y);
            split_tf32(br1.z, bg.z, sm.z); split_tf32(br1.w, bg.w, sm.w);
            *(float4*)(BB + sa + 4) = bg; *(float4*)(BS + sa + 4) = sm;
        }
        __syncthreads();

        if (kc + 1 < NC) {
            const int K0 = (kc + 1) << 4;
            ar0 = *(const float4*)(Ap + K0);
            ar1 = *(const float4*)(Ap + K0 + 4);
            br0 = *(const float4*)(Bp + K0);
            br1 = *(const float4*)(Bp + K0 + 4);
        }

#pragma unroll
        for (int lk8 = 0; lk8 < KCHUNK; lk8 += 8) {
            uint32_t ab[2][4], as_[2][4], bb[8][2], bs[8][2];
#pragma unroll
            for (int mt = 0; mt < 2; mt++) {
                const int r = (wm << 5) + (mt << 4) + gid;
                ab[mt][0]  = __float_as_uint(AB[r * PADS + lk8 + tig]);
                ab[mt][1]  = __float_as_uint(AB[(r + 8) * PADS + lk8 + tig]);
                ab[mt][2]  = __float_as_uint(AB[r * PADS + lk8 + tig + 4]);
                ab[mt][3]  = __float_as_uint(AB[(r + 8) * PADS + lk8 + tig + 4]);
                as_[mt][0] = __float_as_uint(AS[r * PADS + lk8 + tig]);
                as_[mt][1] = __float_as_uint(AS[(r + 8) * PADS + lk8 + tig]);
                as_[mt][2] = __float_as_uint(AS[r * PADS + lk8 + tig + 4]);
                as_[mt][3] = __float_as_uint(AS[(r + 8) * PADS + lk8 + tig + 4]);
            }
#pragma unroll
            for (int nt = 0; nt < 8; nt++) {
                const int nn = (wn << 6) + (nt << 3) + gid;
                bb[nt][0] = __float_as_uint(BB[nn * PADS + lk8 + tig]);
                bb[nt][1] = __float_as_uint(BB[nn * PADS + lk8 + tig + 4]);
                bs[nt][0] = __float_as_uint(BS[nn * PADS + lk8 + tig]);
                bs[nt][1] = __float_as_uint(BS[nn * PADS + lk8 + tig + 4]);
            }
#pragma unroll
            for (int mt = 0; mt < 2; mt++)
#pragma unroll
                for (int nt = 0; nt < 8; nt++) {
                    mma16n8k8(acc[mt][nt], ab[mt], bb[nt]);
                    mma16n8k8(acc[mt][nt], as_[mt], bb[nt]);
                    mma16n8k8(acc[mt][nt], ab[mt], bs[nt]);
                }
        }
        __syncthreads();
    }

    float bias[8][2];
#pragma unroll
    for (int nt = 0; nt < 8; nt++) {
        const int col = n0 + (wn << 6) + (nt << 3) + (tig << 1);
        float v0 = b1[col], v1 = b1[col + 1];
        if (b2) { v0 += b2[col]; v1 += b2[col + 1]; }
        bias[nt][0] = v0; bias[nt][1] = v1;
    }
#pragma unroll
    for (int mt = 0; mt < 2; mt++)
#pragma unroll
        for (int half = 0; half < 2; half++) {
            const int row = m0 + (wm << 5) + (mt << 4) + gid + (half << 3);
            float* crow = C + (size_t)row * N;
#pragma unroll
            for (int nt = 0; nt < 8; nt++) {
                const int col = n0 + (wn << 6) + (nt << 3) + (tig << 1);
                float2 v;
                v.x = acc[mt][nt][half * 2 + 0] + bias[nt][0];
                v.y = acc[mt][nt][half * 2 + 1] + bias[nt][1];
                *(float2*)(crow + col) = v;
            }
        }
}

// ---------------- init ----------------
__global__ void zero_cnt_kernel() {
    if (threadIdx.x < NG) g_cnt[threadIdx.x] = 0;
}

// ---------------- K2: persistent recurrence, N-split warps ----------------
// 128 CTAs = 16 groups x 8 slices, 1/SM (smem 172KB). Warp w owns output cols
// [w*8, w*8+8) over FULL K=512 -> final accumulators in registers, no reduction.
// hT is b-major: staging is a straight 32KB cp.async memcpy (conflict-free);
// compute reads h as broadcast float4 and W as 2-address broadcast ulonglong2.
__global__ void __launch_bounds__(256) rnn_rec_kernel(const float* __restrict__ w_hh)
{
    extern __shared__ float sm[];
    float* w_t = sm;                 // [512][WPAD] k-major W slice
    float* hT  = sm + H_ * WPAD;     // [BT][HSTR]  b-major h tile

    const int tid = threadIdx.x;
    const int g = blockIdx.x >> 3;
    const int s = blockIdx.x & 7;
    const int n0 = s * NS;
    const int b0 = g * BT;

    // cache W_hh slice: w_t[k][n] = w_hh[n0+n][k]
    for (int i = tid; i < NS * H_; i += 256) {
        int n = i >> 9;
        int k = i & (H_ - 1);
        w_t[k * WPAD + n] = w_hh[(size_t)(n0 + n) * H_ + k];
    }

    const int wid = tid >> 5, lane = tid & 31;
    const int b  = lane >> 1;        // batch row (0..15)
    const int nh = lane & 1;         // col half (0/1)
    const int c0 = wid * 8 + nh * 4; // 4 output cols

    const size_t obase = ((size_t)(b0 + b)) * H_ + n0 + c0;
    const uint32_t hT_u32 = smem_u32(hT);

    __syncthreads();

    for (int t = 0; t < T_; t++) {
        // prefetch xp[t] (independent of the flag)
        const float4 xv = __ldcs((const float4*)&g_xp[(size_t)t * B_ * H_ + obase]);

        // --- acquire h_{t-1} ---
        if (t > 0) {
            if (tid == 0) {
                volatile int* c = g_cnt + g;
                while (*c < NSL * t) __nanosleep(40);
                __threadfence();
            }
            __syncthreads();
            const float* hsrc = g_hs + ((size_t)(t - 1) * B_ + b0) * H_;
#pragma unroll
            for (int j = 0; j < 8; j++) {
                int i4 = tid + (j << 8);          // float4 index 0..2047
                int bb = i4 >> 7;                 // batch row
                int k4 = i4 & 127;                // float4 within row
                cp_async16(hT_u32 + (uint32_t)(bb * HSTR + k4 * 4) * 4,
                           hsrc + (size_t)i4 * 4);
            }
            CP_COMMIT_WAIT();
        } else {
            for (int i = tid; i < BT * HSTR; i += 256) hT[i] = 0.0f;
        }
        __syncthreads();

        // --- compute 4 output cols for batch row b over full K ---
        unsigned long long a0 = 0ull, a1 = 0ull;
        const float* hrow = hT + b * HSTR;
        const float* wcol = w_t + c0;
#pragma unroll 4
        for (int k4 = 0; k4 < 128; k4++) {
            const float4 hv = *(const float4*)(hrow + (k4 << 2));
            const float hh[4] = {hv.x, hv.y, hv.z, hv.w};
#pragma unroll
            for (int c = 0; c < 4; c++) {
                const ulonglong2 wv = *(const ulonglong2*)(wcol + ((k4 << 2) + c) * WPAD);
                const unsigned long long hs2 = f32x2_splat(hh[c]);
                a0 = f32x2_fma(hs2, wv.x, a0);
                a1 = f32x2_fma(hs2, wv.y, a1);
            }
        }

        // --- epilogue: add xp, tanh, store h_t (no cross-warp reduce needed) ---
        {
            const float2 lo = f32x2_unpack(a0);
            const float2 hi = f32x2_unpack(a1);
            float4 r;
            r.x = tanhf(lo.x + xv.x);
            r.y = tanhf(lo.y + xv.y);
            r.z = tanhf(hi.x + xv.z);
            r.w = tanhf(hi.y + xv.w);
            *(float4*)&g_hs[(size_t)t * B_ * H_ + obase] = r;
        }
        __syncthreads();

        // --- release slice s of step t ---
        if (tid == 0) {
            __threadfence();
            atomicAdd(&g_cnt[g], 1);
        }
    }
}

// ---------------- launch ----------------
extern "C" void kernel_launch(void* const* d_in, const int* in_sizes, int n_in,
                              void* d_out, int out_size)
{
    const float* x    = (const float*)d_in[0];
    const float* w_ih = (const float*)d_in[1];
    const float* w_hh = (const float*)d_in[2];
    const float* b_ih = (const float*)d_in[3];
    const float* b_hh = (const float*)d_in[4];
    const float* w_fc = (const float*)d_in[5];
    const float* b_fc = (const float*)d_in[6];
    float* out = (float*)d_out;

    float* xp = nullptr;
    float* hs = nullptr;
    cudaGetSymbolAddress((void**)&xp, g_xp);
    cudaGetSymbolAddress((void**)&hs, g_hs);

    const int rec_smem = (H_ * WPAD + BT * HSTR) * (int)sizeof(float); // 172288
    cudaFuncSetAttribute(rnn_rec_kernel, cudaFuncAttributeMaxDynamicSharedMemorySize, rec_smem);
    cudaFuncSetAttribute(mma_gemm_kernel, cudaFuncAttributeMaxDynamicSharedMemorySize, GEMM_SMEM_BYTES);

    const int M = T_ * B_;

    zero_cnt_kernel<<<1, 32>>>();

    // K1: xp = x @ w_ih^T + (b_ih + b_hh)
    mma_gemm_kernel<<<dim3(H_ / 128, M / 128), 256, GEMM_SMEM_BYTES>>>(x, w_ih, b_ih, b_hh, xp, M, H_, I_);

    // K2: recurrence (persistent, 128 CTAs)
    rnn_rec_kernel<<<NG * NSL, 256, rec_smem>>>(w_hh);

    // K3: out = hs @ w_fc^T + b_fc
    mma_gemm_kernel<<<dim3(I_ / 128, M / 128), 256, GEMM_SMEM_BYTES>>>(hs, w_fc, b_fc, nullptr, out, M, I_, H_);
}

// round 11
// speedup vs baseline: 1.0415x; 1.0019x over previous
#include <cuda_runtime.h>
#include <cuda_bf16.h>
#include <cstdint>

// RNNModel: T=512, B=256, I=256, H=512, fp32.
//   K1: xp = x @ w_ih^T + (b_ih + b_hh)      -> mma.sync 3xTF32 GEMM (2 CTA/SM)
//   K2: h_t = tanh(xp_t + h_{t-1} @ w_hh^T)  -> persistent; warps split N (no reduce), b-major hT
//   K3: out = hs @ w_fc^T + b_fc             -> mma.sync 3xTF32 GEMM

#define T_ 512
#define B_ 256
#define I_ 256
#define H_ 512

#define NG  16
#define NSL 8
#define BT  16
#define NS  64
#define WPAD 68
#define HSTR 516   // b-major hT row stride (floats); 516*4 % 16 == 0, bank-spread

__device__ float g_xp[(size_t)T_ * B_ * H_];
__device__ float g_hs[(size_t)T_ * B_ * H_];
__device__ int   g_cnt[NG];

// ---------------- helpers ----------------
__device__ __forceinline__ unsigned long long f32x2_fma(unsigned long long a,
                                                        unsigned long long b,
                                                        unsigned long long c) {
    unsigned long long d;
    asm("fma.rn.f32x2 %0, %1, %2, %3;" : "=l"(d) : "l"(a), "l"(b), "l"(c));
    return d;
}
__device__ __forceinline__ unsigned long long f32x2_splat(float x) {
    unsigned long long d;
    unsigned int xi = __float_as_uint(x);
    asm("mov.b64 %0, {%1, %1};" : "=l"(d) : "r"(xi));
    return d;
}
__device__ __forceinline__ float2 f32x2_unpack(unsigned long long v) {
    unsigned int lo, hi;
    asm("mov.b64 {%0, %1}, %2;" : "=r"(lo), "=r"(hi) : "l"(v));
    float2 r;
    r.x = __uint_as_float(lo);
    r.y = __uint_as_float(hi);
    return r;
}
__device__ __forceinline__ uint32_t smem_u32(const void* p) {
    uint32_t a;
    asm("{ .reg .u64 t; cvta.to.shared.u64 t, %1; cvt.u32.u64 %0, t; }" : "=r"(a) : "l"(p));
    return a;
}
__device__ __forceinline__ void cp_async16(uint32_t saddr, const void* gptr) {
    asm volatile("cp.async.ca.shared.global [%0], [%1], 16;" :: "r"(saddr), "l"(gptr));
}
#define CP_COMMIT_WAIT() \
    asm volatile("cp.async.commit_group;\n\tcp.async.wait_group 0;" ::: "memory")

// ---------------- tf32 helpers ----------------
__device__ __forceinline__ uint32_t cvt_tf32(float x) {
    uint32_t r;
    asm("cvt.rna.tf32.f32 %0, %1;" : "=r"(r) : "f"(x));
    return r;
}
__device__ __forceinline__ void split_tf32(float x, float& big, float& small) {
    big = __uint_as_float(cvt_tf32(x));
    small = __uint_as_float(cvt_tf32(x - big));
}
__device__ __forceinline__ void mma16n8k8(float* c, const uint32_t* a, const uint32_t* b) {
    asm volatile("mma.sync.aligned.m16n8k8.row.col.f32.tf32.tf32.f32 "
        "{%0,%1,%2,%3}, {%4,%5,%6,%7}, {%8,%9}, {%0,%1,%2,%3};"
        : "+f"(c[0]), "+f"(c[1]), "+f"(c[2]), "+f"(c[3])
        : "r"(a[0]), "r"(a[1]), "r"(a[2]), "r"(a[3]), "r"(b[0]), "r"(b[1]));
}

// ---------------- K1/K3: 3xTF32 mma.sync GEMM (now 2 CTA/SM) ----------------
#define KCHUNK 16
#define PADS 20
#define ARRF (128 * PADS)
#define STGF (4 * ARRF)
#define GEMM_SMEM_BYTES (2 * STGF * 4)   // 81920

__global__ void __launch_bounds__(256, 2) mma_gemm_kernel(
    const float* __restrict__ A, const float* __restrict__ Bm,
    const float* __restrict__ b1, const float* __restrict__ b2,
    float* __restrict__ C, int M, int N, int K)
{
    extern __shared__ float sh[];
    const int tid = threadIdx.x;
    const int m0 = blockIdx.y << 7;
    const int n0 = blockIdx.x << 7;
    const int lane = tid & 31, wid = tid >> 5;
    const int gid = lane >> 2, tig = lane & 3;
    const int wm = wid >> 1, wn = wid & 1;

    const int lrow = tid >> 1;
    const int lko  = (tid & 1) << 3;

    const float* Ap = A + (size_t)(m0 + lrow) * K + lko;
    const float* Bp = Bm + (size_t)(n0 + lrow) * K + lko;

    float acc[2][8][4];
#pragma unroll
    for (int mt = 0; mt < 2; mt++)
#pragma unroll
        for (int nt = 0; nt < 8; nt++)
#pragma unroll
            for (int i = 0; i < 4; i++) acc[mt][nt][i] = 0.0f;

    const int NC = K >> 4;

    float4 ar0 = *(const float4*)(Ap);
    float4 ar1 = *(const float4*)(Ap + 4);
    float4 br0 = *(const float4*)(Bp);
    float4 br1 = *(const float4*)(Bp + 4);

    for (int kc = 0; kc < NC; kc++) {
        const int s = kc & 1;
        float* AB = sh + s * STGF;
        float* AS = AB + ARRF;
        float* BB = AS + ARRF;
        float* BS = BB + ARRF;

        {
            float4 bg, sm;
            const int sa = lrow * PADS + lko;
            split_tf32(ar0.x, bg.x, sm.x); split_tf32(ar0.y, bg.y, sm.y);
            split_tf32(ar0.z, bg.z, sm.z); split_tf32(ar0.w, bg.w, sm.w);
            *(float4*)(AB + sa) = bg; *(float4*)(AS + sa) = sm;
            split_tf32(ar1.x, bg.x, sm.x); split_tf32(ar1.y, bg.y, sm.y);
            split_tf32(ar1.z, bg.z, sm.z); split_tf32(ar1.w, bg.w, sm.w);
            *(float4*)(AB + sa + 4) = bg; *(float4*)(AS + sa + 4) = sm;
            split_tf32(br0.x, bg.x, sm.x); split_tf32(br0.y, bg.y, sm.y);
            split_tf32(br0.z, bg.z, sm.z); split_tf32(br0.w, bg.w, sm.w);
            *(float4*)(BB + sa) = bg; *(float4*)(BS + sa) = sm;
            split_tf32(br1.x, bg.x, sm.x); split_tf32(br1.y, bg.y, sm.y);
            split_tf32(br1.z, bg.z, sm.z); split_tf32(br1.w, bg.w, sm.w);
            *(float4*)(BB + sa + 4) = bg; *(float4*)(BS + sa + 4) = sm;
        }
        __syncthreads();

        if (kc + 1 < NC) {
            const int K0 = (kc + 1) << 4;
            ar0 = *(const float4*)(Ap + K0);
            ar1 = *(const float4*)(Ap + K0 + 4);
            br0 = *(const float4*)(Bp + K0);
            br1 = *(const float4*)(Bp + K0 + 4);
        }

#pragma unroll
        for (int lk8 = 0; lk8 < KCHUNK; lk8 += 8) {
            uint32_t ab[2][4], as_[2][4], bb[8][2], bs[8][2];
#pragma unroll
            for (int mt = 0; mt < 2; mt++) {
                const int r = (wm << 5) + (mt << 4) + gid;
                ab[mt][0]  = __float_as_uint(AB[r * PADS + lk8 + tig]);
                ab[mt][1]  = __float_as_uint(AB[(r + 8) * PADS + lk8 + tig]);
                ab[mt][2]  = __float_as_uint(AB[r * PADS + lk8 + tig + 4]);
                ab[mt][3]  = __float_as_uint(AB[(r + 8) * PADS + lk8 + tig + 4]);
                as_[mt][0] = __float_as_uint(AS[r * PADS + lk8 + tig]);
                as_[mt][1] = __float_as_uint(AS[(r + 8) * PADS + lk8 + tig]);
                as_[mt][2] = __float_as_uint(AS[r * PADS + lk8 + tig + 4]);
                as_[mt][3] = __float_as_uint(AS[(r + 8) * PADS + lk8 + tig + 4]);
            }
#pragma unroll
            for (int nt = 0; nt < 8; nt++) {
                const int nn = (wn << 6) + (nt << 3) + gid;
                bb[nt][0] = __float_as_uint(BB[nn * PADS + lk8 + tig]);
                bb[nt][1] = __float_as_uint(BB[nn * PADS + lk8 + tig + 4]);
                bs[nt][0] = __float_as_uint(BS[nn * PADS + lk8 + tig]);
                bs[nt][1] = __float_as_uint(BS[nn * PADS + lk8 + tig + 4]);
            }
#pragma unroll
            for (int mt = 0; mt < 2; mt++)
#pragma unroll
                for (int nt = 0; nt < 8; nt++) {
                    mma16n8k8(acc[mt][nt], ab[mt], bb[nt]);
                    mma16n8k8(acc[mt][nt], as_[mt], bb[nt]);
                    mma16n8k8(acc[mt][nt], ab[mt], bs[nt]);
                }
        }
        __syncthreads();
    }

    float bias[8][2];
#pragma unroll
    for (int nt = 0; nt < 8; nt++) {
        const int col = n0 + (wn << 6) + (nt << 3) + (tig << 1);
        float v0 = b1[col], v1 = b1[col + 1];
        if (b2) { v0 += b2[col]; v1 += b2[col + 1]; }
        bias[nt][0] = v0; bias[nt][1] = v1;
    }
#pragma unroll
    for (int mt = 0; mt < 2; mt++)
#pragma unroll
        for (int half = 0; half < 2; half++) {
            const int row = m0 + (wm << 5) + (mt << 4) + gid + (half << 3);
            float* crow = C + (size_t)row * N;
#pragma unroll
            for (int nt = 0; nt < 8; nt++) {
                const int col = n0 + (wn << 6) + (nt << 3) + (tig << 1);
                float2 v;
                v.x = acc[mt][nt][half * 2 + 0] + bias[nt][0];
                v.y = acc[mt][nt][half * 2 + 1] + bias[nt][1];
                *(float2*)(crow + col) = v;
            }
        }
}

// ---------------- init ----------------
__global__ void zero_cnt_kernel() {
    if (threadIdx.x < NG) g_cnt[threadIdx.x] = 0;
}

// ---------------- K2: persistent recurrence, N-split warps ----------------
// 128 CTAs = 16 groups x 8 slices, 1/SM (smem 172KB). Warp w owns output cols
// [w*8, w*8+8) over FULL K=512 -> final accumulators in registers, no reduction.
// hT is b-major: staging is a straight 32KB cp.async memcpy (conflict-free);
// compute reads h as broadcast float4 and W as 2-address broadcast ulonglong2.
__global__ void __launch_bounds__(256) rnn_rec_kernel(const float* __restrict__ w_hh)
{
    extern __shared__ float sm[];
    float* w_t = sm;                 // [512][WPAD] k-major W slice
    float* hT  = sm + H_ * WPAD;     // [BT][HSTR]  b-major h tile

    const int tid = threadIdx.x;
    const int g = blockIdx.x >> 3;
    const int s = blockIdx.x & 7;
    const int n0 = s * NS;
    const int b0 = g * BT;

    // cache W_hh slice: w_t[k][n] = w_hh[n0+n][k]
    for (int i = tid; i < NS * H_; i += 256) {
        int n = i >> 9;
        int k = i & (H_ - 1);
        w_t[k * WPAD + n] = w_hh[(size_t)(n0 + n) * H_ + k];
    }

    const int wid = tid >> 5, lane = tid & 31;
    const int b  = lane >> 1;        // batch row (0..15)
    const int nh = lane & 1;         // col half (0/1)
    const int c0 = wid * 8 + nh * 4; // 4 output cols

    const size_t obase = ((size_t)(b0 + b)) * H_ + n0 + c0;
    const uint32_t hT_u32 = smem_u32(hT);

    __syncthreads();

    for (int t = 0; t < T_; t++) {
        // prefetch xp[t] (independent of the flag)
        const float4 xv = __ldcs((const float4*)&g_xp[(size_t)t * B_ * H_ + obase]);

        // --- acquire h_{t-1} ---
        if (t > 0) {
            if (tid == 0) {
                volatile int* c = g_cnt + g;
                while (*c < NSL * t) __nanosleep(40);
                __threadfence();
            }
            __syncthreads();
            const float* hsrc = g_hs + ((size_t)(t - 1) * B_ + b0) * H_;
#pragma unroll
            for (int j = 0; j < 8; j++) {
                int i4 = tid + (j << 8);          // float4 index 0..2047
                int bb = i4 >> 7;                 // batch row
                int k4 = i4 & 127;                // float4 within row
                cp_async16(hT_u32 + (uint32_t)(bb * HSTR + k4 * 4) * 4,
                           hsrc + (size_t)i4 * 4);
            }
            CP_COMMIT_WAIT();
        } else {
            for (int i = tid; i < BT * HSTR; i += 256) hT[i] = 0.0f;
        }
        __syncthreads();

        // --- compute 4 output cols for batch row b over full K ---
        unsigned long long a0 = 0ull, a1 = 0ull;
        const float* hrow = hT + b * HSTR;
        const float* wcol = w_t + c0;
#pragma unroll 4
        for (int k4 = 0; k4 < 128; k4++) {
            const float4 hv = *(const float4*)(hrow + (k4 << 2));
            const float hh[4] = {hv.x, hv.y, hv.z, hv.w};
#pragma unroll
            for (int c = 0; c < 4; c++) {
                const ulonglong2 wv = *(const ulonglong2*)(wcol + ((k4 << 2) + c) * WPAD);
                const unsigned long long hs2 = f32x2_splat(hh[c]);
                a0 = f32x2_fma(hs2, wv.x, a0);
                a1 = f32x2_fma(hs2, wv.y, a1);
            }
        }

        // --- epilogue: add xp, tanh, store h_t (no cross-warp reduce needed) ---
        {
            const float2 lo = f32x2_unpack(a0);
            const float2 hi = f32x2_unpack(a1);
            float4 r;
            r.x = tanhf(lo.x + xv.x);
            r.y = tanhf(lo.y + xv.y);
            r.z = tanhf(hi.x + xv.z);
            r.w = tanhf(hi.y + xv.w);
            *(float4*)&g_hs[(size_t)t * B_ * H_ + obase] = r;
        }
        __syncthreads();

        // --- release slice s of step t ---
        if (tid == 0) {
            __threadfence();
            atomicAdd(&g_cnt[g], 1);
        }
    }
}

// ---------------- launch ----------------
extern "C" void kernel_launch(void* const* d_in, const int* in_sizes, int n_in,
                              void* d_out, int out_size)
{
    const float* x    = (const float*)d_in[0];
    const float* w_ih = (const float*)d_in[1];
    const float* w_hh = (const float*)d_in[2];
    const float* b_ih = (const float*)d_in[3];
    const float* b_hh = (const float*)d_in[4];
    const float* w_fc = (const float*)d_in[5];
    const float* b_fc = (const float*)d_in[6];
    float* out = (float*)d_out;

    float* xp = nullptr;
    float* hs = nullptr;
    cudaGetSymbolAddress((void**)&xp, g_xp);
    cudaGetSymbolAddress((void**)&hs, g_hs);

    const int rec_smem = (H_ * WPAD + BT * HSTR) * (int)sizeof(float); // 172288
    cudaFuncSetAttribute(rnn_rec_kernel, cudaFuncAttributeMaxDynamicSharedMemorySize, rec_smem);
    cudaFuncSetAttribute(mma_gemm_kernel, cudaFuncAttributeMaxDynamicSharedMemorySize, GEMM_SMEM_BYTES);

    const int M = T_ * B_;

    zero_cnt_kernel<<<1, 32>>>();

    // K1: xp = x @ w_ih^T + (b_ih + b_hh)
    mma_gemm_kernel<<<dim3(H_ / 128, M / 128), 256, GEMM_SMEM_BYTES>>>(x, w_ih, b_ih, b_hh, xp, M, H_, I_);

    // K2: recurrence (persistent, 128 CTAs)
    rnn_rec_kernel<<<NG * NSL, 256, rec_smem>>>(w_hh);

    // K3: out = hs @ w_fc^T + b_fc
    mma_gemm_kernel<<<dim3(I_ / 128, M / 128), 256, GEMM_SMEM_BYTES>>>(hs, w_fc, b_fc, nullptr, out, M, I_, H_);
}

// round 12
// speedup vs baseline: 1.0432x; 1.0017x over previous
#include <cuda_runtime.h>
#include <cuda_bf16.h>
#include <cstdint>

// RNNModel: T=512, B=256, I=256, H=512, fp32.
//   K1: xp = x @ w_ih^T + (b_ih + b_hh)      -> mma.sync 3xTF32 GEMM (2 CTA/SM)
//   K2: h_t = tanh(xp_t + h_{t-1} @ w_hh^T)  -> persistent; warps split N (no reduce), b-major hT
//   K3: out = hs @ w_fc^T + b_fc             -> mma.sync 3xTF32 GEMM

#define T_ 512
#define B_ 256
#define I_ 256
#define H_ 512

#define NG  16
#define NSL 8
#define BT  16
#define NS  64
#define WPAD 68
#define HSTR 516   // b-major hT row stride (floats); 516*4 % 16 == 0, bank-spread

__device__ float g_xp[(size_t)T_ * B_ * H_];
__device__ float g_hs[(size_t)T_ * B_ * H_];
__device__ int   g_cnt[NG];

// ---------------- helpers ----------------
__device__ __forceinline__ unsigned long long f32x2_fma(unsigned long long a,
                                                        unsigned long long b,
                                                        unsigned long long c) {
    unsigned long long d;
    asm("fma.rn.f32x2 %0, %1, %2, %3;" : "=l"(d) : "l"(a), "l"(b), "l"(c));
    return d;
}
__device__ __forceinline__ unsigned long long f32x2_splat(float x) {
    unsigned long long d;
    unsigned int xi = __float_as_uint(x);
    asm("mov.b64 %0, {%1, %1};" : "=l"(d) : "r"(xi));
    return d;
}
__device__ __forceinline__ float2 f32x2_unpack(unsigned long long v) {
    unsigned int lo, hi;
    asm("mov.b64 {%0, %1}, %2;" : "=r"(lo), "=r"(hi) : "l"(v));
    float2 r;
    r.x = __uint_as_float(lo);
    r.y = __uint_as_float(hi);
    return r;
}
__device__ __forceinline__ uint32_t smem_u32(const void* p) {
    uint32_t a;
    asm("{ .reg .u64 t; cvta.to.shared.u64 t, %1; cvt.u32.u64 %0, t; }" : "=r"(a) : "l"(p));
    return a;
}
__device__ __forceinline__ void cp_async16(uint32_t saddr, const void* gptr) {
    asm volatile("cp.async.ca.shared.global [%0], [%1], 16;" :: "r"(saddr), "l"(gptr));
}
#define CP_COMMIT_WAIT() \
    asm volatile("cp.async.commit_group;\n\tcp.async.wait_group 0;" ::: "memory")

// ---------------- tf32 helpers ----------------
__device__ __forceinline__ uint32_t cvt_tf32(float x) {
    uint32_t r;
    asm("cvt.rna.tf32.f32 %0, %1;" : "=r"(r) : "f"(x));
    return r;
}
__device__ __forceinline__ void split_tf32(float x, float& big, float& small) {
    big = __uint_as_float(cvt_tf32(x));
    small = __uint_as_float(cvt_tf32(x - big));
}
__device__ __forceinline__ void mma16n8k8(float* c, const uint32_t* a, const uint32_t* b) {
    asm volatile("mma.sync.aligned.m16n8k8.row.col.f32.tf32.tf32.f32 "
        "{%0,%1,%2,%3}, {%4,%5,%6,%7}, {%8,%9}, {%0,%1,%2,%3};"
        : "+f"(c[0]), "+f"(c[1]), "+f"(c[2]), "+f"(c[3])
        : "r"(a[0]), "r"(a[1]), "r"(a[2]), "r"(a[3]), "r"(b[0]), "r"(b[1]));
}

// ---------------- K1/K3: 3xTF32 mma.sync GEMM (now 2 CTA/SM) ----------------
#define KCHUNK 16
#define PADS 20
#define ARRF (128 * PADS)
#define STGF (4 * ARRF)
#define GEMM_SMEM_BYTES (2 * STGF * 4)   // 81920

__global__ void __launch_bounds__(256, 2) mma_gemm_kernel(
    const float* __restrict__ A, const float* __restrict__ Bm,
    const float* __restrict__ b1, const float* __restrict__ b2,
    float* __restrict__ C, int M, int N, int K)
{
    extern __shared__ float sh[];
    const int tid = threadIdx.x;
    const int m0 = blockIdx.y << 7;
    const int n0 = blockIdx.x << 7;
    const int lane = tid & 31, wid = tid >> 5;
    const int gid = lane >> 2, tig = lane & 3;
    const int wm = wid >> 1, wn = wid & 1;

    const int lrow = tid >> 1;
    const int lko  = (tid & 1) << 3;

    const float* Ap = A + (size_t)(m0 + lrow) * K + lko;
    const float* Bp = Bm + (size_t)(n0 + lrow) * K + lko;

    float acc[2][8][4];
#pragma unroll
    for (int mt = 0; mt < 2; mt++)
#pragma unroll
        for (int nt = 0; nt < 8; nt++)
#pragma unroll
            for (int i = 0; i < 4; i++) acc[mt][nt][i] = 0.0f;

    const int NC = K >> 4;

    float4 ar0 = *(const float4*)(Ap);
    float4 ar1 = *(const float4*)(Ap + 4);
    float4 br0 = *(const float4*)(Bp);
    float4 br1 = *(const float4*)(Bp + 4);

    for (int kc = 0; kc < NC; kc++) {
        const int s = kc & 1;
        float* AB = sh + s * STGF;
        float* AS = AB + ARRF;
        float* BB = AS + ARRF;
        float* BS = BB + ARRF;

        {
            float4 bg, sm;
            const int sa = lrow * PADS + lko;
            split_tf32(ar0.x, bg.x, sm.x); split_tf32(ar0.y, bg.y, sm.y);
            split_tf32(ar0.z, bg.z, sm.z); split_tf32(ar0.w, bg.w, sm.w);
            *(float4*)(AB + sa) = bg; *(float4*)(AS + sa) = sm;
            split_tf32(ar1.x, bg.x, sm.x); split_tf32(ar1.y, bg.y, sm.y);
            split_tf32(ar1.z, bg.z, sm.z); split_tf32(ar1.w, bg.w, sm.w);
            *(float4*)(AB + sa + 4) = bg; *(float4*)(AS + sa + 4) = sm;
            split_tf32(br0.x, bg.x, sm.x); split_tf32(br0.y, bg.y, sm.y);
            split_tf32(br0.z, bg.z, sm.z); split_tf32(br0.w, bg.w, sm.w);
            *(float4*)(BB + sa) = bg; *(float4*)(BS + sa) = sm;
            split_tf32(br1.x, bg.x, sm.x); split_tf32(br1.y, bg.y, sm.y);
            split_tf32(br1.z, bg.z, sm.z); split_tf32(br1.w, bg.w, sm.w);
            *(float4*)(BB + sa + 4) = bg; *(float4*)(BS + sa + 4) = sm;
        }
        __syncthreads();

        if (kc + 1 < NC) {
            const int K0 = (kc + 1) << 4;
            ar0 = *(const float4*)(Ap + K0);
            ar1 = *(const float4*)(Ap + K0 + 4);
            br0 = *(const float4*)(Bp + K0);
            br1 = *(const float4*)(Bp + K0 + 4);
        }

#pragma unroll
        for (int lk8 = 0; lk8 < KCHUNK; lk8 += 8) {
            uint32_t ab[2][4], as_[2][4], bb[8][2], bs[8][2];
#pragma unroll
            for (int mt = 0; mt < 2; mt++) {
                const int r = (wm << 5) + (mt << 4) + gid;
                ab[mt][0]  = __float_as_uint(AB[r * PADS + lk8 + tig]);
                ab[mt][1]  = __float_as_uint(AB[(r + 8) * PADS + lk8 + tig]);
                ab[mt][2]  = __float_as_uint(AB[r * PADS + lk8 + tig + 4]);
                ab[mt][3]  = __float_as_uint(AB[(r + 8) * PADS + lk8 + tig + 4]);
                as_[mt][0] = __float_as_uint(AS[r * PADS + lk8 + tig]);
                as_[mt][1] = __float_as_uint(AS[(r + 8) * PADS + lk8 + tig]);
                as_[mt][2] = __float_as_uint(AS[r * PADS + lk8 + tig + 4]);
                as_[mt][3] = __float_as_uint(AS[(r + 8) * PADS + lk8 + tig + 4]);
            }
#pragma unroll
            for (int nt = 0; nt < 8; nt++) {
                const int nn = (wn << 6) + (nt << 3) + gid;
                bb[nt][0] = __float_as_uint(BB[nn * PADS + lk8 + tig]);
                bb[nt][1] = __float_as_uint(BB[nn * PADS + lk8 + tig + 4]);
                bs[nt][0] = __float_as_uint(BS[nn * PADS + lk8 + tig]);
                bs[nt][1] = __float_as_uint(BS[nn * PADS + lk8 + tig + 4]);
            }
#pragma unroll
            for (int mt = 0; mt < 2; mt++)
#pragma unroll
                for (int nt = 0; nt < 8; nt++) {
                    mma16n8k8(acc[mt][nt], ab[mt], bb[nt]);
                    mma16n8k8(acc[mt][nt], as_[mt], bb[nt]);
                    mma16n8k8(acc[mt][nt], ab[mt], bs[nt]);
                }
        }
        __syncthreads();
    }

    float bias[8][2];
#pragma unroll
    for (int nt = 0; nt < 8; nt++) {
        const int col = n0 + (wn << 6) + (nt << 3) + (tig << 1);
        float v0 = b1[col], v1 = b1[col + 1];
        if (b2) { v0 += b2[col]; v1 += b2[col + 1]; }
        bias[nt][0] = v0; bias[nt][1] = v1;
    }
#pragma unroll
    for (int mt = 0; mt < 2; mt++)
#pragma unroll
        for (int half = 0; half < 2; half++) {
            const int row = m0 + (wm << 5) + (mt << 4) + gid + (half << 3);
            float* crow = C + (size_t)row * N;
#pragma unroll
            for (int nt = 0; nt < 8; nt++) {
                const int col = n0 + (wn << 6) + (nt << 3) + (tig << 1);
                float2 v;
                v.x = acc[mt][nt][half * 2 + 0] + bias[nt][0];
                v.y = acc[mt][nt][half * 2 + 1] + bias[nt][1];
                *(float2*)(crow + col) = v;
            }
        }
}

// ---------------- init ----------------
__global__ void zero_cnt_kernel() {
    if (threadIdx.x < NG) g_cnt[threadIdx.x] = 0;
}

// ---------------- K2: persistent recurrence, N-split warps ----------------
// 128 CTAs = 16 groups x 8 slices, 1/SM (smem 172KB). Warp w owns output cols
// [w*8, w*8+8) over FULL K=512 -> final accumulators in registers, no reduction.
// hT is b-major: staging is a straight 32KB cp.async memcpy (conflict-free);
// compute reads h as broadcast float4 and W as 2-address broadcast ulonglong2.
__global__ void __launch_bounds__(256) rnn_rec_kernel(const float* __restrict__ w_hh)
{
    extern __shared__ float sm[];
    float* w_t = sm;                 // [512][WPAD] k-major W slice
    float* hT  = sm + H_ * WPAD;     // [BT][HSTR]  b-major h tile

    const int tid = threadIdx.x;
    const int g = blockIdx.x >> 3;
    const int s = blockIdx.x & 7;
    const int n0 = s * NS;
    const int b0 = g * BT;

    // cache W_hh slice: w_t[k][n] = w_hh[n0+n][k]
    for (int i = tid; i < NS * H_; i += 256) {
        int n = i >> 9;
        int k = i & (H_ - 1);
        w_t[k * WPAD + n] = w_hh[(size_t)(n0 + n) * H_ + k];
    }

    const int wid = tid >> 5, lane = tid & 31;
    const int b  = lane >> 1;        // batch row (0..15)
    const int nh = lane & 1;         // col half (0/1)
    const int c0 = wid * 8 + nh * 4; // 4 output cols

    const size_t obase = ((size_t)(b0 + b)) * H_ + n0 + c0;
    const uint32_t hT_u32 = smem_u32(hT);

    __syncthreads();

    for (int t = 0; t < T_; t++) {
        // prefetch xp[t] (independent of the flag)
        const float4 xv = __ldcs((const float4*)&g_xp[(size_t)t * B_ * H_ + obase]);

        // --- acquire h_{t-1} ---
        if (t > 0) {
            if (tid == 0) {
                volatile int* c = g_cnt + g;
                while (*c < NSL * t) __nanosleep(40);
                __threadfence();
            }
            __syncthreads();
            const float* hsrc = g_hs + ((size_t)(t - 1) * B_ + b0) * H_;
#pragma unroll
            for (int j = 0; j < 8; j++) {
                int i4 = tid + (j << 8);          // float4 index 0..2047
                int bb = i4 >> 7;                 // batch row
                int k4 = i4 & 127;                // float4 within row
                cp_async16(hT_u32 + (uint32_t)(bb * HSTR + k4 * 4) * 4,
                           hsrc + (size_t)i4 * 4);
            }
            CP_COMMIT_WAIT();
        } else {
            for (int i = tid; i < BT * HSTR; i += 256) hT[i] = 0.0f;
        }
        __syncthreads();

        // --- compute 4 output cols for batch row b over full K ---
        unsigned long long a0 = 0ull, a1 = 0ull;
        const float* hrow = hT + b * HSTR;
        const float* wcol = w_t + c0;
#pragma unroll 4
        for (int k4 = 0; k4 < 128; k4++) {
            const float4 hv = *(const float4*)(hrow + (k4 << 2));
            const float hh[4] = {hv.x, hv.y, hv.z, hv.w};
#pragma unroll
            for (int c = 0; c < 4; c++) {
                const ulonglong2 wv = *(const ulonglong2*)(wcol + ((k4 << 2) + c) * WPAD);
                const unsigned long long hs2 = f32x2_splat(hh[c]);
                a0 = f32x2_fma(hs2, wv.x, a0);
                a1 = f32x2_fma(hs2, wv.y, a1);
            }
        }

        // --- epilogue: add xp, tanh, store h_t (no cross-warp reduce needed) ---
        {
            const float2 lo = f32x2_unpack(a0);
            const float2 hi = f32x2_unpack(a1);
            float4 r;
            r.x = tanhf(lo.x + xv.x);
            r.y = tanhf(lo.y + xv.y);
            r.z = tanhf(hi.x + xv.z);
            r.w = tanhf(hi.y + xv.w);
            *(float4*)&g_hs[(size_t)t * B_ * H_ + obase] = r;
        }
        __syncthreads();

        // --- release slice s of step t ---
        if (tid == 0) {
            __threadfence();
            atomicAdd(&g_cnt[g], 1);
        }
    }
}

// ---------------- launch ----------------
extern "C" void kernel_launch(void* const* d_in, const int* in_sizes, int n_in,
                              void* d_out, int out_size)
{
    const float* x    = (const float*)d_in[0];
    const float* w_ih = (const float*)d_in[1];
    const float* w_hh = (const float*)d_in[2];
    const float* b_ih = (const float*)d_in[3];
    const float* b_hh = (const float*)d_in[4];
    const float* w_fc = (const float*)d_in[5];
    const float* b_fc = (const float*)d_in[6];
    float* out = (float*)d_out;

    float* xp = nullptr;
    float* hs = nullptr;
    cudaGetSymbolAddress((void**)&xp, g_xp);
    cudaGetSymbolAddress((void**)&hs, g_hs);

    const int rec_smem = (H_ * WPAD + BT * HSTR) * (int)sizeof(float); // 172288
    cudaFuncSetAttribute(rnn_rec_kernel, cudaFuncAttributeMaxDynamicSharedMemorySize, rec_smem);
    cudaFuncSetAttribute(mma_gemm_kernel, cudaFuncAttributeMaxDynamicSharedMemorySize, GEMM_SMEM_BYTES);

    const int M = T_ * B_;

    zero_cnt_kernel<<<1, 32>>>();

    // K1: xp = x @ w_ih^T + (b_ih + b_hh)
    mma_gemm_kernel<<<dim3(H_ / 128, M / 128), 256, GEMM_SMEM_BYTES>>>(x, w_ih, b_ih, b_hh, xp, M, H_, I_);

    // K2: recurrence (persistent, 128 CTAs)
    rnn_rec_kernel<<<NG * NSL, 256, rec_smem>>>(w_hh);

    // K3: out = hs @ w_fc^T + b_fc
    mma_gemm_kernel<<<dim3(I_ / 128, M / 128), 256, GEMM_SMEM_BYTES>>>(hs, w_fc, b_fc, nullptr, out, M, I_, H_);
}